// round 2
// baseline (speedup 1.0000x reference)
#include <cuda_runtime.h>
#include <cuda_bf16.h>

#define RES 512
#define RANK 32
#define CELLS (RES * RES)
#define PLANE_ELEMS (CELLS * RANK)
#define N_POINTS (8192 * 128)

// Transposed + bf16-quantized grids: layout [plane][cell(y*RES+x)][rank]
__device__ __nv_bfloat16 g_tp[3][PLANE_ELEMS];

// ---------------------------------------------------------------------------
// Kernel 1: [RANK, H, W] f32  ->  [H*W, RANK] bf16 transpose via smem tile.
// Block = 256 threads handles 32 consecutive cells x all 32 ranks.
// Reads coalesced along W; writes coalesced along rank*cell.
// ---------------------------------------------------------------------------
__global__ void transpose_kernel(const float* __restrict__ gxy,
                                 const float* __restrict__ gxz,
                                 const float* __restrict__ gyz) {
    __shared__ float tile[RANK][33];  // +1 pad: conflict-free column reads

    const int plane = blockIdx.y;
    const float* __restrict__ src = (plane == 0) ? gxy : (plane == 1) ? gxz : gyz;
    const int c0 = blockIdx.x * 32;

    const int t = threadIdx.x;
    const int w = t >> 5;   // warp 0..7
    const int l = t & 31;   // lane

#pragma unroll
    for (int i = 0; i < 4; i++) {
        const int r = w + i * 8;
        tile[r][l] = src[(size_t)r * CELLS + c0 + l];
    }
    __syncthreads();

    __nv_bfloat16* __restrict__ dst = g_tp[plane];
#pragma unroll
    for (int k = 0; k < 2; k++) {
        const int item = t + k * 256;
        const int pair = item & 15;   // rank pair 0..15
        const int cell = item >> 4;   // local cell 0..31
        __nv_bfloat162 v = __floats2bfloat162_rn(tile[2 * pair][cell],
                                                 tile[2 * pair + 1][cell]);
        *reinterpret_cast<__nv_bfloat162*>(dst + (size_t)(c0 + cell) * RANK + 2 * pair) = v;
    }
}

// ---------------------------------------------------------------------------
// Kernel 2: triplane sample. Half-warp (16 lanes) per point, lane = rank pair.
// ---------------------------------------------------------------------------
struct Corners {
    int o00, o01, o10, o11;  // offsets in bf162 units
    float wx, wy;
};

__device__ __forceinline__ Corners make_corners(float cx, float cy) {
    // Match reference: x = (c + 1) * 0.5 * (W - 1), floor before clamp.
    const float gx = ((cx + 1.0f) * 0.5f) * (float)(RES - 1);
    const float gy = ((cy + 1.0f) * 0.5f) * (float)(RES - 1);
    const float fx = floorf(gx);
    const float fy = floorf(gy);
    Corners c;
    c.wx = gx - fx;
    c.wy = gy - fy;
    int x0 = min(max(__float2int_rd(gx), 0), RES - 1);
    int y0 = min(max(__float2int_rd(gy), 0), RES - 1);
    int x1 = min(x0 + 1, RES - 1);
    int y1 = min(y0 + 1, RES - 1);
    // cell*RANK elements = cell*(RANK/2) in bf162 units
    c.o00 = (y0 * RES + x0) * (RANK / 2);
    c.o01 = (y0 * RES + x1) * (RANK / 2);
    c.o10 = (y1 * RES + x0) * (RANK / 2);
    c.o11 = (y1 * RES + x1) * (RANK / 2);
    return c;
}

__device__ __forceinline__ float2 bilin(__nv_bfloat162 v00, __nv_bfloat162 v01,
                                        __nv_bfloat162 v10, __nv_bfloat162 v11,
                                        float wx, float wy) {
    const float2 f00 = __bfloat1622float2(v00);
    const float2 f01 = __bfloat1622float2(v01);
    const float2 f10 = __bfloat1622float2(v10);
    const float2 f11 = __bfloat1622float2(v11);
    const float w00 = (1.0f - wx) * (1.0f - wy);
    const float w01 = wx * (1.0f - wy);
    const float w10 = (1.0f - wx) * wy;
    const float w11 = wx * wy;
    float2 r;
    r.x = f00.x * w00 + f01.x * w01 + f10.x * w10 + f11.x * w11;
    r.y = f00.y * w00 + f01.y * w01 + f10.y * w10 + f11.y * w11;
    return r;
}

__global__ void __launch_bounds__(256) sample_kernel(const float* __restrict__ pts,
                                                     const float* __restrict__ aabb,
                                                     float* __restrict__ out) {
    const int tid = blockIdx.x * blockDim.x + threadIdx.x;
    const int lane = tid & 31;
    const int half = lane >> 4;       // which point within the warp
    const int r2 = lane & 15;         // rank pair index 0..15
    const int point = (tid >> 5) * 2 + half;

    // Broadcast loads (all 16 lanes of a half-warp read the same address)
    const float px = __ldg(&pts[point * 3 + 0]);
    const float py = __ldg(&pts[point * 3 + 1]);
    const float pz = __ldg(&pts[point * 3 + 2]);

    const float a0x = __ldg(&aabb[0]), a0y = __ldg(&aabb[1]), a0z = __ldg(&aabb[2]);
    const float a1x = __ldg(&aabb[3]), a1y = __ldg(&aabb[4]), a1z = __ldg(&aabb[5]);

    const float nx = (px - a0x) * (2.0f / (a1x - a0x)) - 1.0f;
    const float ny = (py - a0y) * (2.0f / (a1y - a0y)) - 1.0f;
    const float nz = (pz - a0z) * (2.0f / (a1z - a0z)) - 1.0f;

    const Corners cxy = make_corners(nx, ny);
    const Corners cxz = make_corners(nx, nz);
    const Corners cyz = make_corners(ny, nz);

    const __nv_bfloat162* __restrict__ P0 =
        reinterpret_cast<const __nv_bfloat162*>(g_tp[0]);
    const __nv_bfloat162* __restrict__ P1 =
        reinterpret_cast<const __nv_bfloat162*>(g_tp[1]);
    const __nv_bfloat162* __restrict__ P2 =
        reinterpret_cast<const __nv_bfloat162*>(g_tp[2]);

    // Issue all 12 loads up front for maximal MLP
    const __nv_bfloat162 a00 = P0[cxy.o00 + r2];
    const __nv_bfloat162 a01 = P0[cxy.o01 + r2];
    const __nv_bfloat162 a10 = P0[cxy.o10 + r2];
    const __nv_bfloat162 a11 = P0[cxy.o11 + r2];
    const __nv_bfloat162 b00 = P1[cxz.o00 + r2];
    const __nv_bfloat162 b01 = P1[cxz.o01 + r2];
    const __nv_bfloat162 b10 = P1[cxz.o10 + r2];
    const __nv_bfloat162 b11 = P1[cxz.o11 + r2];
    const __nv_bfloat162 c00 = P2[cyz.o00 + r2];
    const __nv_bfloat162 c01 = P2[cyz.o01 + r2];
    const __nv_bfloat162 c10 = P2[cyz.o10 + r2];
    const __nv_bfloat162 c11 = P2[cyz.o11 + r2];

    const float2 sxy = bilin(a00, a01, a10, a11, cxy.wx, cxy.wy);
    const float2 sxz = bilin(b00, b01, b10, b11, cxz.wx, cxz.wy);
    const float2 syz = bilin(c00, c01, c10, c11, cyz.wx, cyz.wy);

    float sum = sxy.x * sxz.x * syz.x + sxy.y * sxz.y * syz.y;

    // Reduce across the 16-lane half-warp
    sum += __shfl_down_sync(0xffffffffu, sum, 8, 16);
    sum += __shfl_down_sync(0xffffffffu, sum, 4, 16);
    sum += __shfl_down_sync(0xffffffffu, sum, 2, 16);
    sum += __shfl_down_sync(0xffffffffu, sum, 1, 16);

    if (r2 == 0) {
        out[point] = expf(sum * (1.0f / (float)RANK));
    }
}

extern "C" void kernel_launch(void* const* d_in, const int* in_sizes, int n_in,
                              void* d_out, int out_size) {
    const float* pts  = (const float*)d_in[0];
    const float* gxy  = (const float*)d_in[1];
    const float* gxz  = (const float*)d_in[2];
    const float* gyz  = (const float*)d_in[3];
    const float* aabb = (const float*)d_in[4];
    float* out = (float*)d_out;

    // 1) Transpose + bf16 quantize all three planes
    transpose_kernel<<<dim3(CELLS / 32, 3), 256>>>(gxy, gxz, gyz);

    // 2) Sample: 2 points per warp, 16 points per 256-thread block
    sample_kernel<<<N_POINTS / 16, 256>>>(pts, aabb, out);
}

// round 3
// speedup vs baseline: 1.7996x; 1.7996x over previous
#include <cuda_runtime.h>
#include <cuda_bf16.h>

#define RES 512
#define RANK 32
#define CELLS (RES * RES)
#define PLANE_ELEMS (CELLS * RANK)
#define N_POINTS (8192 * 128)

// Transposed + bf16-quantized grids: layout [plane][cell(y*RES+x)][rank]
__device__ __nv_bfloat16 g_tp[3][PLANE_ELEMS];

// ---------------------------------------------------------------------------
// Kernel 1: [RANK, H, W] f32  ->  [H*W, RANK] bf16 transpose via smem tile.
// ---------------------------------------------------------------------------
__global__ void transpose_kernel(const float* __restrict__ gxy,
                                 const float* __restrict__ gxz,
                                 const float* __restrict__ gyz) {
    __shared__ float tile[RANK][33];

    const int plane = blockIdx.y;
    const float* __restrict__ src = (plane == 0) ? gxy : (plane == 1) ? gxz : gyz;
    const int c0 = blockIdx.x * 32;

    const int t = threadIdx.x;
    const int w = t >> 5;
    const int l = t & 31;

#pragma unroll
    for (int i = 0; i < 4; i++) {
        const int r = w + i * 8;
        tile[r][l] = src[(size_t)r * CELLS + c0 + l];
    }
    __syncthreads();

    __nv_bfloat16* __restrict__ dst = g_tp[plane];
#pragma unroll
    for (int k = 0; k < 2; k++) {
        const int item = t + k * 256;
        const int pair = item & 15;
        const int cell = item >> 4;
        __nv_bfloat162 v = __floats2bfloat162_rn(tile[2 * pair][cell],
                                                 tile[2 * pair + 1][cell]);
        *reinterpret_cast<__nv_bfloat162*>(dst + (size_t)(c0 + cell) * RANK + 2 * pair) = v;
    }
}

// ---------------------------------------------------------------------------
// Kernel 2: triplane sample. 4 lanes per point; lane = rank-quad (8 bf16 = 16B).
// Warp covers 8 points -> scalar work amortized 4x better than half-warp scheme.
// ---------------------------------------------------------------------------
struct Corners {
    int c00, c01, c10, c11;  // cell indices
    float wx, wy;
};

__device__ __forceinline__ Corners make_corners(float cx, float cy) {
    const float gx = ((cx + 1.0f) * 0.5f) * (float)(RES - 1);
    const float gy = ((cy + 1.0f) * 0.5f) * (float)(RES - 1);
    Corners c;
    c.wx = gx - floorf(gx);
    c.wy = gy - floorf(gy);
    int x0 = min(max(__float2int_rd(gx), 0), RES - 1);
    int y0 = min(max(__float2int_rd(gy), 0), RES - 1);
    int x1 = min(x0 + 1, RES - 1);
    int y1 = min(y0 + 1, RES - 1);
    c.c00 = y0 * RES + x0;
    c.c01 = y0 * RES + x1;
    c.c10 = y1 * RES + x0;
    c.c11 = y1 * RES + x1;
    return c;
}

// Load 8 bf16 (16 B) for cell, rank-quad r4
__device__ __forceinline__ uint4 ldq(const __nv_bfloat16* __restrict__ base,
                                     int cell, int r4) {
    return *reinterpret_cast<const uint4*>(
        reinterpret_cast<const char*>(base) + ((size_t)cell << 6) + ((size_t)r4 << 4));
}

// 8-wide bilinear: out[i] = sum of 4 corners with weights; values unpacked from uint4
__device__ __forceinline__ void bilin8(const uint4& v00, const uint4& v01,
                                       const uint4& v10, const uint4& v11,
                                       float wx, float wy, float2 out[4]) {
    const float w00 = (1.0f - wx) * (1.0f - wy);
    const float w01 = wx * (1.0f - wy);
    const float w10 = (1.0f - wx) * wy;
    const float w11 = wx * wy;
    const unsigned int* a = &v00.x;
    const unsigned int* b = &v01.x;
    const unsigned int* c = &v10.x;
    const unsigned int* d = &v11.x;
#pragma unroll
    for (int i = 0; i < 4; i++) {
        const float2 fa = __bfloat1622float2(*reinterpret_cast<const __nv_bfloat162*>(&a[i]));
        const float2 fb = __bfloat1622float2(*reinterpret_cast<const __nv_bfloat162*>(&b[i]));
        const float2 fc = __bfloat1622float2(*reinterpret_cast<const __nv_bfloat162*>(&c[i]));
        const float2 fd = __bfloat1622float2(*reinterpret_cast<const __nv_bfloat162*>(&d[i]));
        out[i].x = fa.x * w00 + fb.x * w01 + fc.x * w10 + fd.x * w11;
        out[i].y = fa.y * w00 + fb.y * w01 + fc.y * w10 + fd.y * w11;
    }
}

__global__ void __launch_bounds__(256) sample_kernel(const float* __restrict__ pts,
                                                     const float* __restrict__ aabb,
                                                     float* __restrict__ out) {
    const int tid = blockIdx.x * blockDim.x + threadIdx.x;
    const int r4 = tid & 3;            // rank quad 0..3
    const int point = tid >> 2;        // 4 lanes per point

    const float px = __ldg(&pts[point * 3 + 0]);
    const float py = __ldg(&pts[point * 3 + 1]);
    const float pz = __ldg(&pts[point * 3 + 2]);

    const float a0x = __ldg(&aabb[0]), a0y = __ldg(&aabb[1]), a0z = __ldg(&aabb[2]);
    const float a1x = __ldg(&aabb[3]), a1y = __ldg(&aabb[4]), a1z = __ldg(&aabb[5]);

    const float nx = (px - a0x) * (2.0f / (a1x - a0x)) - 1.0f;
    const float ny = (py - a0y) * (2.0f / (a1y - a0y)) - 1.0f;
    const float nz = (pz - a0z) * (2.0f / (a1z - a0z)) - 1.0f;

    const Corners cxy = make_corners(nx, ny);
    const Corners cxz = make_corners(nx, nz);
    const Corners cyz = make_corners(ny, nz);

    const __nv_bfloat16* __restrict__ P0 = g_tp[0];
    const __nv_bfloat16* __restrict__ P1 = g_tp[1];
    const __nv_bfloat16* __restrict__ P2 = g_tp[2];

    // All 12 corner loads issued up front for maximal MLP
    const uint4 A00 = ldq(P0, cxy.c00, r4);
    const uint4 A01 = ldq(P0, cxy.c01, r4);
    const uint4 A10 = ldq(P0, cxy.c10, r4);
    const uint4 A11 = ldq(P0, cxy.c11, r4);
    const uint4 B00 = ldq(P1, cxz.c00, r4);
    const uint4 B01 = ldq(P1, cxz.c01, r4);
    const uint4 B10 = ldq(P1, cxz.c10, r4);
    const uint4 B11 = ldq(P1, cxz.c11, r4);
    const uint4 C00 = ldq(P2, cyz.c00, r4);
    const uint4 C01 = ldq(P2, cyz.c01, r4);
    const uint4 C10 = ldq(P2, cyz.c10, r4);
    const uint4 C11 = ldq(P2, cyz.c11, r4);

    float2 sxy[4], sxz[4], syz[4];
    bilin8(A00, A01, A10, A11, cxy.wx, cxy.wy, sxy);
    bilin8(B00, B01, B10, B11, cxz.wx, cxz.wy, sxz);
    bilin8(C00, C01, C10, C11, cyz.wx, cyz.wy, syz);

    float sum = 0.0f;
#pragma unroll
    for (int i = 0; i < 4; i++) {
        sum += sxy[i].x * sxz[i].x * syz[i].x;
        sum += sxy[i].y * sxz[i].y * syz[i].y;
    }

    // Reduce across the 4-lane group
    sum += __shfl_xor_sync(0xffffffffu, sum, 1);
    sum += __shfl_xor_sync(0xffffffffu, sum, 2);

    if (r4 == 0) {
        out[point] = expf(sum * (1.0f / (float)RANK));
    }
}

extern "C" void kernel_launch(void* const* d_in, const int* in_sizes, int n_in,
                              void* d_out, int out_size) {
    const float* pts  = (const float*)d_in[0];
    const float* gxy  = (const float*)d_in[1];
    const float* gxz  = (const float*)d_in[2];
    const float* gyz  = (const float*)d_in[3];
    const float* aabb = (const float*)d_in[4];
    float* out = (float*)d_out;

    transpose_kernel<<<dim3(CELLS / 32, 3), 256>>>(gxy, gxz, gyz);

    // 4 lanes/point -> 64 points per 256-thread block
    sample_kernel<<<N_POINTS / 64, 256>>>(pts, aabb, out);
}

// round 4
// speedup vs baseline: 2.0999x; 1.1669x over previous
#include <cuda_runtime.h>
#include <cuda_fp16.h>

#define RES 512
#define RANK 32
#define CELLS (RES * RES)
#define PLANE_ELEMS (CELLS * RANK)
#define N_POINTS (8192 * 128)

// Transposed + fp16-quantized grids: layout [plane][cell(y*RES+x)][rank]
__device__ __half g_tp[3][PLANE_ELEMS];

// Encoded per-dim bbox of raw pts: [min_x,min_y,min_z, max_x,max_y,max_z]
__device__ unsigned int g_bbox[6];

// Order-preserving float<->uint encode (works for negatives)
__device__ __forceinline__ unsigned int encodeF(float f) {
    unsigned int b = __float_as_uint(f);
    return (b & 0x80000000u) ? ~b : (b | 0x80000000u);
}
__device__ __forceinline__ float decodeF(unsigned int u) {
    return (u & 0x80000000u) ? __uint_as_float(u ^ 0x80000000u)
                             : __uint_as_float(~u);
}

// ---------------------------------------------------------------------------
// Kernel 0: reset bbox accumulators
// ---------------------------------------------------------------------------
__global__ void init_kernel() {
    int t = threadIdx.x;
    if (t < 3) g_bbox[t] = 0xFFFFFFFFu;       // min-enc init (encoded +inf)
    else if (t < 6) g_bbox[t] = 0u;           // max-enc init (encoded -inf)
}

// ---------------------------------------------------------------------------
// Kernel 1: per-dimension min/max of raw pts.
// stride = 384*256 = 98304 is divisible by 3 -> each thread sees ONE dim only.
// ---------------------------------------------------------------------------
__global__ void __launch_bounds__(256) bbox_kernel(const float* __restrict__ pts) {
    const int t = blockIdx.x * 256 + threadIdx.x;
    const int stride = 384 * 256;
    const int dim = t % 3;
    float mn = 3.0e38f, mx = -3.0e38f;
    for (int i = t; i < N_POINTS * 3; i += stride) {
        const float v = __ldg(&pts[i]);
        mn = fminf(mn, v);
        mx = fmaxf(mx, v);
    }
    __shared__ unsigned int smn[3], smx[3];
    if (threadIdx.x < 3) { smn[threadIdx.x] = 0xFFFFFFFFu; smx[threadIdx.x] = 0u; }
    __syncthreads();
    atomicMin(&smn[dim], encodeF(mn));
    atomicMax(&smx[dim], encodeF(mx));
    __syncthreads();
    if (threadIdx.x < 3) {
        atomicMin(&g_bbox[threadIdx.x], smn[threadIdx.x]);
        atomicMax(&g_bbox[3 + threadIdx.x], smx[threadIdx.x]);
    }
}

// ---------------------------------------------------------------------------
// Kernel 2: [RANK, H, W] f32 -> [H*W, RANK] fp16 transpose, bbox-gated.
// Block = 256 threads handles 32 consecutive cells (one row segment) x 32 ranks.
// ---------------------------------------------------------------------------
__global__ void __launch_bounds__(256) transpose_kernel(const float* __restrict__ gxy,
                                                        const float* __restrict__ gxz,
                                                        const float* __restrict__ gyz,
                                                        const float* __restrict__ aabb) {
    const int plane = blockIdx.y;
    const int c0 = blockIdx.x * 32;
    const int row = c0 >> 9;
    const int col0 = c0 & (RES - 1);

    // plane 0 (xy): cols<-x(0) rows<-y(1); plane 1 (xz): cols<-x(0) rows<-z(2);
    // plane 2 (yz): cols<-y(1) rows<-z(2)
    const int cdim = (plane == 2) ? 1 : 0;
    const int rdim = (plane == 0) ? 1 : 2;

    // grid coord g = (v - a0) / (a1 - a0) * (RES-1)
    {
        const float a0c = aabb[cdim], sc = (float)(RES - 1) / (aabb[3 + cdim] - aabb[cdim]);
        const float a0r = aabb[rdim], sr = (float)(RES - 1) / (aabb[3 + rdim] - aabb[rdim]);
        const float gminc = (decodeF(g_bbox[cdim]) - a0c) * sc;
        const float gmaxc = (decodeF(g_bbox[3 + cdim]) - a0c) * sc;
        const float gminr = (decodeF(g_bbox[rdim]) - a0r) * sr;
        const float gmaxr = (decodeF(g_bbox[3 + rdim]) - a0r) * sr;
        const int cmin = min(max(__float2int_rd(gminc), 0), RES - 1);
        const int cmax = min(min(max(__float2int_rd(gmaxc), 0), RES - 1) + 1, RES - 1);
        const int rmin = min(max(__float2int_rd(gminr), 0), RES - 1);
        const int rmax = min(min(max(__float2int_rd(gmaxr), 0), RES - 1) + 1, RES - 1);
        if (row < rmin || row > rmax || col0 > cmax || col0 + 31 < cmin) return;
    }

    __shared__ float tile[RANK][33];
    const float* __restrict__ src = (plane == 0) ? gxy : (plane == 1) ? gxz : gyz;

    const int t = threadIdx.x;
    const int w = t >> 5;
    const int l = t & 31;

#pragma unroll
    for (int i = 0; i < 4; i++) {
        const int r = w + i * 8;
        tile[r][l] = src[(size_t)r * CELLS + c0 + l];
    }
    __syncthreads();

    __half* __restrict__ dst = g_tp[plane];
#pragma unroll
    for (int k = 0; k < 2; k++) {
        const int item = t + k * 256;
        const int pair = item & 15;   // rank pair 0..15
        const int cell = item >> 4;   // local cell 0..31
        __half2 v = __floats2half2_rn(tile[2 * pair][cell], tile[2 * pair + 1][cell]);
        *reinterpret_cast<__half2*>(dst + (size_t)(c0 + cell) * RANK + 2 * pair) = v;
    }
}

// ---------------------------------------------------------------------------
// Kernel 3: triplane sample. 4 lanes/point; lane = rank-quad (8 fp16 = 16B).
// All math in half2 (HFMA2/HMUL2) - no per-element f32 conversions.
// ---------------------------------------------------------------------------
struct Corners {
    unsigned int o00, o01, o10, o11;  // byte offsets (cell<<6)
    float wx, wy;
};

__device__ __forceinline__ Corners make_corners(float cx, float cy) {
    const float gx = ((cx + 1.0f) * 0.5f) * (float)(RES - 1);
    const float gy = ((cy + 1.0f) * 0.5f) * (float)(RES - 1);
    Corners c;
    c.wx = gx - floorf(gx);
    c.wy = gy - floorf(gy);
    const int x0 = min(max(__float2int_rd(gx), 0), RES - 1);
    const int y0 = min(max(__float2int_rd(gy), 0), RES - 1);
    const int dx = (min(x0 + 1, RES - 1) - x0) << 6;         // 0 or 64 bytes
    const int dy = (min(y0 + 1, RES - 1) - y0) << (6 + 9);   // 0 or 512*64 bytes
    c.o00 = (unsigned int)((y0 * RES + x0) << 6);
    c.o01 = c.o00 + dx;
    c.o10 = c.o00 + dy;
    c.o11 = c.o10 + dx;
    return c;
}

__device__ __forceinline__ uint4 ldq(const __half* __restrict__ base,
                                     unsigned int byte_off, int r4) {
    return *reinterpret_cast<const uint4*>(
        reinterpret_cast<const char*>(base) + byte_off + ((unsigned)r4 << 4));
}

__device__ __forceinline__ void bilin8_h(const uint4& v00, const uint4& v01,
                                         const uint4& v10, const uint4& v11,
                                         __half2 w00, __half2 w01,
                                         __half2 w10, __half2 w11,
                                         __half2 s[4]) {
    const __half2* a = reinterpret_cast<const __half2*>(&v00);
    const __half2* b = reinterpret_cast<const __half2*>(&v01);
    const __half2* c = reinterpret_cast<const __half2*>(&v10);
    const __half2* d = reinterpret_cast<const __half2*>(&v11);
#pragma unroll
    for (int i = 0; i < 4; i++) {
        __half2 t = __hmul2(a[i], w00);
        t = __hfma2(b[i], w01, t);
        t = __hfma2(c[i], w10, t);
        s[i] = __hfma2(d[i], w11, t);
    }
}

__global__ void __launch_bounds__(256) sample_kernel(const float* __restrict__ pts,
                                                     const float* __restrict__ aabb,
                                                     float* __restrict__ out) {
    const int tid = blockIdx.x * blockDim.x + threadIdx.x;
    const int r4 = tid & 3;            // rank quad 0..3
    const int point = tid >> 2;        // 4 lanes per point

    const float px = __ldg(&pts[point * 3 + 0]);
    const float py = __ldg(&pts[point * 3 + 1]);
    const float pz = __ldg(&pts[point * 3 + 2]);

    const float a0x = __ldg(&aabb[0]), a0y = __ldg(&aabb[1]), a0z = __ldg(&aabb[2]);
    const float a1x = __ldg(&aabb[3]), a1y = __ldg(&aabb[4]), a1z = __ldg(&aabb[5]);

    const float nx = (px - a0x) * (2.0f / (a1x - a0x)) - 1.0f;
    const float ny = (py - a0y) * (2.0f / (a1y - a0y)) - 1.0f;
    const float nz = (pz - a0z) * (2.0f / (a1z - a0z)) - 1.0f;

    const Corners cxy = make_corners(nx, ny);
    const Corners cxz = make_corners(nx, nz);
    const Corners cyz = make_corners(ny, nz);

    const __half* __restrict__ P0 = g_tp[0];
    const __half* __restrict__ P1 = g_tp[1];
    const __half* __restrict__ P2 = g_tp[2];

    // All 12 corner loads issued up front for maximal MLP
    const uint4 A00 = ldq(P0, cxy.o00, r4);
    const uint4 A01 = ldq(P0, cxy.o01, r4);
    const uint4 A10 = ldq(P0, cxy.o10, r4);
    const uint4 A11 = ldq(P0, cxy.o11, r4);
    const uint4 B00 = ldq(P1, cxz.o00, r4);
    const uint4 B01 = ldq(P1, cxz.o01, r4);
    const uint4 B10 = ldq(P1, cxz.o10, r4);
    const uint4 B11 = ldq(P1, cxz.o11, r4);
    const uint4 C00 = ldq(P2, cyz.o00, r4);
    const uint4 C01 = ldq(P2, cyz.o01, r4);
    const uint4 C10 = ldq(P2, cyz.o10, r4);
    const uint4 C11 = ldq(P2, cyz.o11, r4);

    // Bilinear weights as broadcast half2
    const float wx0 = cxy.wx, wy0 = cxy.wy;
    const float wx1 = cxz.wx, wy1 = cxz.wy;
    const float wx2 = cyz.wx, wy2 = cyz.wy;

    __half2 sxy[4], sxz[4], syz[4];
    bilin8_h(A00, A01, A10, A11,
             __float2half2_rn((1.0f - wx0) * (1.0f - wy0)),
             __float2half2_rn(wx0 * (1.0f - wy0)),
             __float2half2_rn((1.0f - wx0) * wy0),
             __float2half2_rn(wx0 * wy0), sxy);
    bilin8_h(B00, B01, B10, B11,
             __float2half2_rn((1.0f - wx1) * (1.0f - wy1)),
             __float2half2_rn(wx1 * (1.0f - wy1)),
             __float2half2_rn((1.0f - wx1) * wy1),
             __float2half2_rn(wx1 * wy1), sxz);
    bilin8_h(C00, C01, C10, C11,
             __float2half2_rn((1.0f - wx2) * (1.0f - wy2)),
             __float2half2_rn(wx2 * (1.0f - wy2)),
             __float2half2_rn((1.0f - wx2) * wy2),
             __float2half2_rn(wx2 * wy2), syz);

    // Triple product + accumulate in half2
    __half2 acc = __hmul2(__hmul2(sxy[0], sxz[0]), syz[0]);
#pragma unroll
    for (int i = 1; i < 4; i++) {
        acc = __hfma2(__hmul2(sxy[i], sxz[i]), syz[i], acc);
    }
    float sum = __low2float(acc) + __high2float(acc);

    // Reduce across the 4-lane group
    sum += __shfl_xor_sync(0xffffffffu, sum, 1);
    sum += __shfl_xor_sync(0xffffffffu, sum, 2);

    if (r4 == 0) {
        out[point] = expf(sum * (1.0f / (float)RANK));
    }
}

extern "C" void kernel_launch(void* const* d_in, const int* in_sizes, int n_in,
                              void* d_out, int out_size) {
    const float* pts  = (const float*)d_in[0];
    const float* gxy  = (const float*)d_in[1];
    const float* gxz  = (const float*)d_in[2];
    const float* gyz  = (const float*)d_in[3];
    const float* aabb = (const float*)d_in[4];
    float* out = (float*)d_out;

    init_kernel<<<1, 32>>>();
    bbox_kernel<<<384, 256>>>(pts);
    transpose_kernel<<<dim3(CELLS / 32, 3), 256>>>(gxy, gxz, gyz, aabb);
    sample_kernel<<<N_POINTS / 64, 256>>>(pts, aabb, out);
}